// round 17
// baseline (speedup 1.0000x reference)
#include <cuda_runtime.h>
#include <cuda_bf16.h>
#include <cuda_fp16.h>
#include <math.h>
#include <stdint.h>

#define BATCH 4
#define SEQ   512
#define DM    1024
#define NH    16
#define NL    8
#define VOCAB 32000
#define HDIM  64
#define DFF   4096
#define MROWS (BATCH*SEQ)
#define DM3   (3*DM)

// fp32 scratch
__device__ float g_x  [MROWS*DM];
__device__ float g_t0 [MROWS*DM];
// fp16 weights / activations
__device__ __half g_hWqkv[NL*DM*DM3];
__device__ __half g_hWo[NL*DM*DM];
__device__ __half g_hW1[NL*DM*DFF];
__device__ __half g_hW2[NL*DFF*DM];
__device__ __half g_hWfc[DM*VOCAB];
__device__ __half g_hx  [MROWS*DM];
__device__ __half g_ht3 [MROWS*DM];
__device__ __half g_hf1 [MROWS*DFF];
__device__ __half g_hqkv[MROWS*DM3];
__device__ float  g_bqkv[NL*DM3];

__device__ __forceinline__ uint32_t h2pk(float x, float y){
    __half2 h = __floats2half2_rn(x, y);
    return *(uint32_t*)&h;
}

__global__ void cvt_f2h(const float* __restrict__ s, __half* __restrict__ d, int n){
    int i = (blockIdx.x * blockDim.x + threadIdx.x) * 4;
    if (i >= n) return;
    float4 v = *(const float4*)(s + i);
    uint2 h = make_uint2(h2pk(v.x, v.y), h2pk(v.z, v.w));
    *(uint2*)(d + i) = h;
}

__global__ void pack_qkv_w(const float* __restrict__ Wq, const float* __restrict__ Wk,
                           const float* __restrict__ Wv, __half* __restrict__ d)
{
    long long i = ((long long)blockIdx.x * blockDim.x + threadIdx.x) * 4;
    if (i >= (long long)NL * DM * DM3) return;
    int l = (int)(i / ((long long)DM * DM3));
    long long rem = i % ((long long)DM * DM3);
    int k = (int)(rem / DM3);
    int c = (int)(rem % DM3);
    const float* src = (c < DM) ? Wq : ((c < 2*DM) ? Wk : Wv);
    int sc = c % DM;
    float4 v = *(const float4*)(src + (size_t)l * DM * DM + (size_t)k * DM + sc);
    uint2 h = make_uint2(h2pk(v.x, v.y), h2pk(v.z, v.w));
    *(uint2*)(d + i) = h;
}
__global__ void pack_qkv_b(const float* __restrict__ bq, const float* __restrict__ bk,
                           const float* __restrict__ bv, float* __restrict__ d)
{
    int i = blockIdx.x * blockDim.x + threadIdx.x;
    if (i >= NL * DM3) return;
    int l = i / DM3, c = i % DM3;
    const float* src = (c < DM) ? bq : ((c < 2*DM) ? bk : bv);
    d[i] = src[(size_t)l * DM + (c % DM)];
}

__global__ void embed_kernel(const int* __restrict__ tokens,
                             const float* __restrict__ emb,
                             const float* __restrict__ pe,
                             float* __restrict__ x, __half* __restrict__ hx)
{
    int idx = blockIdx.x * blockDim.x + threadIdx.x;
    if (idx >= MROWS * DM) return;
    int d  = idx % DM;
    int nt = idx / DM;
    int n  = nt / SEQ;
    int tok = tokens[nt];
    float v = emb[(size_t)tok * DM + d] + pe[(size_t)n * DM + d];
    x[idx] = v;
    hx[idx] = __float2half_rn(v);
}

// ---------------- shared PTX helpers ----------------------------------------
__device__ __forceinline__ uint32_t cvta_smem(const void* p){
    uint32_t a;
    asm("{ .reg .u64 t; cvta.to.shared.u64 t, %1; cvt.u32.u64 %0, t; }" : "=r"(a) : "l"(p));
    return a;
}
__device__ __forceinline__ void cpa16(uint32_t daddr, const void* g){
    asm volatile("cp.async.cg.shared.global [%0], [%1], 16;" :: "r"(daddr), "l"(g));
}
__device__ __forceinline__ void cp_commit(){ asm volatile("cp.async.commit_group;"); }
__device__ __forceinline__ void cp_wait1(){ asm volatile("cp.async.wait_group 1;"); }
__device__ __forceinline__ void cp_wait0(){ asm volatile("cp.async.wait_group 0;"); }
__device__ __forceinline__ void ldm4(uint32_t* r, uint32_t addr){
    asm volatile("ldmatrix.sync.aligned.m8n8.x4.shared.b16 {%0,%1,%2,%3}, [%4];"
                 : "=r"(r[0]), "=r"(r[1]), "=r"(r[2]), "=r"(r[3]) : "r"(addr));
}
__device__ __forceinline__ void ldm4t(uint32_t* r, uint32_t addr){
    asm volatile("ldmatrix.sync.aligned.m8n8.x4.trans.shared.b16 {%0,%1,%2,%3}, [%4];"
                 : "=r"(r[0]), "=r"(r[1]), "=r"(r[2]), "=r"(r[3]) : "r"(addr));
}
__device__ __forceinline__ void mma_f16(float* c, const uint32_t* a, const uint32_t* b){
    asm volatile(
        "mma.sync.aligned.m16n8k16.row.col.f32.f16.f16.f32 "
        "{%0,%1,%2,%3}, {%4,%5,%6,%7}, {%8,%9}, {%0,%1,%2,%3};"
        : "+f"(c[0]), "+f"(c[1]), "+f"(c[2]), "+f"(c[3])
        : "r"(a[0]), "r"(a[1]), "r"(a[2]), "r"(a[3]), "r"(b[0]), "r"(b[1]));
}

// ===== fp16 cp.async GEMM ====================================================
// Tile (AMT*32) x (NPW*32), BK=64, 3-stage ring, 256 thr (8 warps 2Mx4N).
// Warp tile (AMT*16) x (NPW*8). NPW=4 -> N=128; NPW=8 -> N=256 (warp 64x64).
#define PADA_H 72

template<bool RELU, bool OUTH, int AMT, int NPW>
__global__ void __launch_bounds__(256, 1)
hgemm(const __half* __restrict__ A, const __half* __restrict__ B,
      const float* __restrict__ bias, void* __restrict__ Cout,
      int Nn, int K)
{
    constexpr int BM   = AMT * 32;
    constexpr int BN   = NPW * 32;
    constexpr int PADB = BN + 8;
    constexpr int A_BY = BM * PADA_H * 2;
    constexpr int B_BY = 64 * PADB * 2;
    constexpr int STG  = A_BY + B_BY;
    constexpr int BCH  = BN / 8;
    constexpr int BP   = 64 * BCH / 256;

    extern __shared__ __half smem[];
    const int tid = threadIdx.x, lane = tid & 31, warp = tid >> 5;
    const int warp_m = warp & 1, warp_n = warp >> 1;
    const int mbase = blockIdx.x * BM, nbase = blockIdx.y * BN;

    const __half* Ag = A + (size_t)mbase * K;
    const __half* Bg = B + nbase;
    const int NC = K >> 6;

    const uint32_t smem_u = cvta_smem(smem);
    const int a_row = tid >> 3, a_c8 = tid & 7;

    const int g = lane >> 2, tig = lane & 3;
    const int sel = lane >> 3, l7 = lane & 7;
    uint32_t a_rel[AMT], b_rel[NPW/2];
#pragma unroll
    for (int mt = 0; mt < AMT; mt++){
        int row = warp_m * (AMT*16) + mt * 16 + (sel & 1) * 8 + l7;
        a_rel[mt] = (uint32_t)(row * (PADA_H*2)) + (uint32_t)((sel >> 1) * 16);
    }
#pragma unroll
    for (int np2 = 0; np2 < NPW/2; np2++){
        int krow = (sel & 1) * 8 + l7;
        int ncol = warp_n * (NPW*8) + np2 * 16 + (sel >> 1) * 8;
        b_rel[np2] = (uint32_t)A_BY + (uint32_t)(krow * (PADB*2)) + (uint32_t)(ncol * 2);
    }

    float acc[AMT][NPW][4];
#pragma unroll
    for (int mt = 0; mt < AMT; mt++)
#pragma unroll
        for (int np = 0; np < NPW; np++)
#pragma unroll
            for (int i = 0; i < 4; i++) acc[mt][np][i] = 0.f;

    auto issue_stage = [&](int chunk, int buf){
        uint32_t base = smem_u + (uint32_t)buf * STG;
        const __half* As = Ag + (size_t)chunk * 64;
#pragma unroll
        for (int p = 0; p < AMT; p++){
            int row = a_row + p * 32;
            cpa16(base + row * (PADA_H*2) + a_c8 * 16,
                  As + (size_t)row * K + a_c8 * 8);
        }
        const __half* Bs = Bg + (size_t)(chunk * 64) * Nn;
#pragma unroll
        for (int p = 0; p < BP; p++){
            int idx = tid + p * 256;
            int row = idx / BCH, c16 = idx % BCH;
            cpa16(base + A_BY + row * (PADB*2) + c16 * 16,
                  Bs + (size_t)row * Nn + c16 * 8);
        }
        cp_commit();
    };

    issue_stage(0, 0);
    if (NC > 1) issue_stage(1, 1);

    int buf = 0;
    for (int c = 0; c < NC; c++){
        if (c + 1 < NC) cp_wait1(); else cp_wait0();
        __syncthreads();
        if (c + 2 < NC){
            int nb = buf + 2; if (nb >= 3) nb -= 3;
            issue_stage(c + 2, nb);
        }

        const uint32_t sbase = smem_u + (uint32_t)buf * STG;
#pragma unroll
        for (int ks = 0; ks < 4; ks++){
            uint32_t af[4*AMT], bf[2*NPW];
#pragma unroll
            for (int mt = 0; mt < AMT; mt++)
                ldm4(&af[4*mt], sbase + a_rel[mt] + ks * 32);
#pragma unroll
            for (int np2 = 0; np2 < NPW/2; np2++)
                ldm4t(&bf[4*np2], sbase + b_rel[np2] + ks * 16 * (PADB*2));
#pragma unroll
            for (int mt = 0; mt < AMT; mt++)
#pragma unroll
                for (int np = 0; np < NPW; np++)
                    mma_f16(acc[mt][np], &af[4*mt], &bf[2*np]);
        }

        if (++buf == 3) buf = 0;
    }

#pragma unroll
    for (int mt = 0; mt < AMT; mt++){
        int row0 = mbase + warp_m * (AMT*16) + mt * 16 + g;
#pragma unroll
        for (int np = 0; np < NPW; np++){
            int col = nbase + warp_n * (NPW*8) + np * 8 + 2 * tig;
            float b0 = bias[col], b1 = bias[col + 1];
            float2 v0 = make_float2(acc[mt][np][0] + b0, acc[mt][np][1] + b1);
            float2 v1 = make_float2(acc[mt][np][2] + b0, acc[mt][np][3] + b1);
            if (RELU){
                v0.x = fmaxf(v0.x, 0.f); v0.y = fmaxf(v0.y, 0.f);
                v1.x = fmaxf(v1.x, 0.f); v1.y = fmaxf(v1.y, 0.f);
            }
            if (OUTH){
                __half* Ch = (__half*)Cout;
                *(uint32_t*)&Ch[(size_t)row0 * Nn + col]       = h2pk(v0.x, v0.y);
                *(uint32_t*)&Ch[(size_t)(row0 + 8) * Nn + col] = h2pk(v1.x, v1.y);
            } else {
                float* C = (float*)Cout;
                *(float2*)&C[(size_t)row0 * Nn + col]       = v0;
                *(float2*)&C[(size_t)(row0 + 8) * Nn + col] = v1;
            }
        }
    }
}

#define SMEM_N256 (3*(128*PADA_H*2 + 64*(256+8)*2))    // 156672
#define SMEM_N128_M64 (3*(64*PADA_H*2 + 64*(128+8)*2)) // 79872

// ===== tensor-core causal flash attention (fp16 in, fp32 softmax/accum) ======
#define PADH 72

__global__ void __launch_bounds__(128)
fattn(const __half* __restrict__ qkv, __half* __restrict__ o)
{
    __shared__ __half sQ[64*PADH];
    __shared__ __half sK[2][64*PADH];
    __shared__ __half sV[2][64*PADH];

    const int n = blockIdx.z, h = blockIdx.y, qb = blockIdx.x;
    const int tid = threadIdx.x, lane = tid & 31, warp = tid >> 5;
    const int g = lane >> 2, tig = lane & 3;
    const int sel = lane >> 3, l7 = lane & 7;

    const __half* Qg = qkv + ((size_t)(n*SEQ + qb*64))*DM3 + h*HDIM;
    const __half* Kg = qkv + ((size_t)(n*SEQ))*DM3 + DM + h*HDIM;
    const __half* Vg = qkv + ((size_t)(n*SEQ))*DM3 + 2*DM + h*HDIM;

    {
        int row = tid >> 1, c0 = (tid & 1) * 4;
        const uint4* src = (const uint4*)(Qg + (size_t)row * DM3);
        uint4* dst = (uint4*)(sQ + row * PADH);
#pragma unroll
        for (int i = 0; i < 4; i++) dst[c0 + i] = src[c0 + i];
    }
    __syncthreads();

    uint32_t qf[4][4];
    {
        uint32_t base = cvta_smem(sQ);
#pragma unroll
        for (int kc = 0; kc < 4; kc++){
            uint32_t addr = base + (uint32_t)((warp*16 + (sel&1)*8 + l7) * (PADH*2))
                          + (uint32_t)((sel>>1)*16 + kc*32);
            ldm4(qf[kc], addr);
        }
    }

    auto issue_kv = [&](int t, int buf){
        int row = tid >> 1, c0 = (tid & 1) * 4;
        const __half* kg = Kg + (size_t)(t*64 + row) * DM3;
        const __half* vg = Vg + (size_t)(t*64 + row) * DM3;
        uint32_t kb = cvta_smem(sK[buf]) + row * (PADH*2);
        uint32_t vb = cvta_smem(sV[buf]) + row * (PADH*2);
#pragma unroll
        for (int i = 0; i < 4; i++){
            cpa16(kb + (c0+i)*16, kg + (c0+i)*8);
            cpa16(vb + (c0+i)*16, vg + (c0+i)*8);
        }
        cp_commit();
    };

    float m0 = -1e30f, m1 = -1e30f, l0 = 0.f, l1 = 0.f;
    float oacc[8][4];
#pragma unroll
    for (int nb = 0; nb < 8; nb++)
#pragma unroll
        for (int i = 0; i < 4; i++) oacc[nb][i] = 0.f;

    const int nt = qb + 1;
    issue_kv(0, 0);

    for (int t = 0; t < nt; t++){
        if (t + 1 < nt){ issue_kv(t + 1, (t + 1) & 1); cp_wait1(); }
        else cp_wait0();
        __syncthreads();
        const int buf = t & 1;

        float sc[8][4];
#pragma unroll
        for (int nb = 0; nb < 8; nb++)
#pragma unroll
            for (int i = 0; i < 4; i++) sc[nb][i] = 0.f;

        uint32_t kbase = cvta_smem(sK[buf]);
#pragma unroll
        for (int kc = 0; kc < 4; kc++){
            uint32_t kf[16];
#pragma unroll
            for (int nb16 = 0; nb16 < 4; nb16++){
                uint32_t addr = kbase + (uint32_t)((nb16*16 + (sel>>1)*8 + l7) * (PADH*2))
                              + (uint32_t)((sel&1)*16 + kc*32);
                ldm4(&kf[nb16*4], addr);
            }
#pragma unroll
            for (int nb16 = 0; nb16 < 4; nb16++){
                mma_f16(sc[2*nb16],   qf[kc], &kf[nb16*4]);
                mma_f16(sc[2*nb16+1], qf[kc], &kf[nb16*4 + 2]);
            }
        }

#pragma unroll
        for (int nb = 0; nb < 8; nb++)
#pragma unroll
            for (int i = 0; i < 4; i++) sc[nb][i] *= 0.125f;
        if (t == qb){
            int row0 = warp*16 + g, row1 = row0 + 8;
#pragma unroll
            for (int nb = 0; nb < 8; nb++){
                int cb = nb*8 + 2*tig;
                if (cb     > row0) sc[nb][0] = -1e30f;
                if (cb + 1 > row0) sc[nb][1] = -1e30f;
                if (cb     > row1) sc[nb][2] = -1e30f;
                if (cb + 1 > row1) sc[nb][3] = -1e30f;
            }
        }

        float tm0 = -1e30f, tm1 = -1e30f;
#pragma unroll
        for (int nb = 0; nb < 8; nb++){
            tm0 = fmaxf(tm0, fmaxf(sc[nb][0], sc[nb][1]));
            tm1 = fmaxf(tm1, fmaxf(sc[nb][2], sc[nb][3]));
        }
        tm0 = fmaxf(tm0, __shfl_xor_sync(0xffffffffu, tm0, 1));
        tm0 = fmaxf(tm0, __shfl_xor_sync(0xffffffffu, tm0, 2));
        tm1 = fmaxf(tm1, __shfl_xor_sync(0xffffffffu, tm1, 1));
        tm1 = fmaxf(tm1, __shfl_xor_sync(0xffffffffu, tm1, 2));

        float nm0 = fmaxf(m0, tm0), nm1 = fmaxf(m1, tm1);
        float cf0 = __expf(m0 - nm0), cf1 = __expf(m1 - nm1);
        l0 *= cf0; l1 *= cf1;
#pragma unroll
        for (int nb = 0; nb < 8; nb++){
            oacc[nb][0] *= cf0; oacc[nb][1] *= cf0;
            oacc[nb][2] *= cf1; oacc[nb][3] *= cf1;
        }
        float rs0 = 0.f, rs1 = 0.f;
#pragma unroll
        for (int nb = 0; nb < 8; nb++){
            sc[nb][0] = __expf(sc[nb][0] - nm0);
            sc[nb][1] = __expf(sc[nb][1] - nm0);
            sc[nb][2] = __expf(sc[nb][2] - nm1);
            sc[nb][3] = __expf(sc[nb][3] - nm1);
            rs0 += sc[nb][0] + sc[nb][1];
            rs1 += sc[nb][2] + sc[nb][3];
        }
        rs0 += __shfl_xor_sync(0xffffffffu, rs0, 1);
        rs0 += __shfl_xor_sync(0xffffffffu, rs0, 2);
        rs1 += __shfl_xor_sync(0xffffffffu, rs1, 1);
        rs1 += __shfl_xor_sync(0xffffffffu, rs1, 2);
        l0 += rs0; l1 += rs1; m0 = nm0; m1 = nm1;

        uint32_t vbase = cvta_smem(sV[buf]);
#pragma unroll
        for (int kc = 0; kc < 4; kc++){
            uint32_t pa[4];
            pa[0] = h2pk(sc[2*kc][0],   sc[2*kc][1]);
            pa[1] = h2pk(sc[2*kc][2],   sc[2*kc][3]);
            pa[2] = h2pk(sc[2*kc+1][0], sc[2*kc+1][1]);
            pa[3] = h2pk(sc[2*kc+1][2], sc[2*kc+1][3]);
            uint32_t vf[16];
#pragma unroll
            for (int db = 0; db < 4; db++){
                uint32_t addr = vbase + (uint32_t)((kc*16 + (sel&1)*8 + l7) * (PADH*2))
                              + (uint32_t)(db*32 + (sel>>1)*16);
                ldm4t(&vf[db*4], addr);
            }
#pragma unroll
            for (int db = 0; db < 4; db++){
                mma_f16(oacc[2*db],   pa, &vf[db*4]);
                mma_f16(oacc[2*db+1], pa, &vf[db*4 + 2]);
            }
        }
        __syncthreads();
    }

    float inv0 = 1.f / l0, inv1 = 1.f / l1;
    int row0 = n*SEQ + qb*64 + warp*16 + g;
#pragma unroll
    for (int nb = 0; nb < 8; nb++){
        int col = h*HDIM + nb*8 + 2*tig;
        *(uint32_t*)&o[(size_t)row0 * DM + col] =
            h2pk(oacc[nb][0]*inv0, oacc[nb][1]*inv0);
        *(uint32_t*)&o[(size_t)(row0 + 8) * DM + col] =
            h2pk(oacc[nb][2]*inv1, oacc[nb][3]*inv1);
    }
}

// ---- residual + LayerNorm (single pass over o via registers) ----------------
__global__ void __launch_bounds__(256)
ln_residual(float* __restrict__ x, const float* __restrict__ o,
            const float* __restrict__ g, const float* __restrict__ b,
            __half* __restrict__ hx)
{
    __shared__ float red[256];
    __shared__ float s_mean, s_rstd;
    int row = blockIdx.x;
    int tid = threadIdx.x;
    const float4* o4 = (const float4*)(o + (size_t)row * DM);
    float4*       x4 = (float4*)(x + (size_t)row * DM);
    __half*      hrow = hx + (size_t)row * DM;

    float4 ov = o4[tid];
    float s = ov.x + ov.y + ov.z + ov.w;
    red[tid] = s; __syncthreads();
    for (int off = 128; off > 0; off >>= 1) {
        if (tid < off) red[tid] += red[tid + off];
        __syncthreads();
    }
    if (tid == 0) s_mean = red[0] * (1.f / DM);
    __syncthreads();
    float mean = s_mean;

    float dx = ov.x - mean, dy = ov.y - mean, dz = ov.z - mean, dw = ov.w - mean;
    red[tid] = dx*dx + dy*dy + dz*dz + dw*dw; __syncthreads();
    for (int off = 128; off > 0; off >>= 1) {
        if (tid < off) red[tid] += red[tid + off];
        __syncthreads();
    }
    if (tid == 0) s_rstd = rsqrtf(red[0] * (1.f / DM) + 1e-5f);
    __syncthreads();
    float rstd = s_rstd;

    const float4 gv = ((const float4*)g)[tid];
    const float4 bv = ((const float4*)b)[tid];
    float4 xv = x4[tid];
    xv.x += dx * rstd * gv.x + bv.x;
    xv.y += dy * rstd * gv.y + bv.y;
    xv.z += dz * rstd * gv.z + bv.z;
    xv.w += dw * rstd * gv.w + bv.w;
    x4[tid] = xv;
    uint2 hh = make_uint2(h2pk(xv.x, xv.y), h2pk(xv.z, xv.w));
    *(uint2*)(hrow + tid * 4) = hh;
}

// ---------------- launch ----------------------------------------------------
extern "C" void kernel_launch(void* const* d_in, const int* in_sizes, int n_in,
                              void* d_out, int out_size)
{
    const int*   tokens = (const int*)  d_in[0];
    const float* emb    = (const float*)d_in[1];
    const float* pe     = (const float*)d_in[2];
    const float* Wq     = (const float*)d_in[3];
    const float* bq     = (const float*)d_in[4];
    const float* Wk     = (const float*)d_in[5];
    const float* bk     = (const float*)d_in[6];
    const float* Wv     = (const float*)d_in[7];
    const float* bv     = (const float*)d_in[8];
    const float* Wo     = (const float*)d_in[9];
    const float* bo     = (const float*)d_in[10];
    const float* g1     = (const float*)d_in[11];
    const float* be1    = (const float*)d_in[12];
    const float* W1     = (const float*)d_in[13];
    const float* b1     = (const float*)d_in[14];
    const float* W2     = (const float*)d_in[15];
    const float* b2     = (const float*)d_in[16];
    const float* g2     = (const float*)d_in[17];
    const float* be2    = (const float*)d_in[18];
    const float* Wfc    = (const float*)d_in[19];
    const float* bfc    = (const float*)d_in[20];
    float* out = (float*)d_out;

    float *x, *t0, *bqkv;
    __half *hWqkv, *hWo, *hW1, *hW2, *hWfc, *hx, *ht3, *hf1, *hqkv;
    cudaGetSymbolAddress((void**)&x,   g_x);
    cudaGetSymbolAddress((void**)&t0,  g_t0);
    cudaGetSymbolAddress((void**)&bqkv, g_bqkv);
    cudaGetSymbolAddress((void**)&hWqkv, g_hWqkv);
    cudaGetSymbolAddress((void**)&hWo, g_hWo);
    cudaGetSymbolAddress((void**)&hW1, g_hW1);
    cudaGetSymbolAddress((void**)&hW2, g_hW2);
    cudaGetSymbolAddress((void**)&hWfc, g_hWfc);
    cudaGetSymbolAddress((void**)&hx,  g_hx);
    cudaGetSymbolAddress((void**)&ht3, g_ht3);
    cudaGetSymbolAddress((void**)&hf1, g_hf1);
    cudaGetSymbolAddress((void**)&hqkv, g_hqkv);

    cudaFuncSetAttribute(hgemm<false,true,4,8>,
                         cudaFuncAttributeMaxDynamicSharedMemorySize, SMEM_N256);
    cudaFuncSetAttribute(hgemm<true,true,4,8>,
                         cudaFuncAttributeMaxDynamicSharedMemorySize, SMEM_N256);
    cudaFuncSetAttribute(hgemm<false,false,4,8>,
                         cudaFuncAttributeMaxDynamicSharedMemorySize, SMEM_N256);
    cudaFuncSetAttribute(hgemm<false,false,2,4>,
                         cudaFuncAttributeMaxDynamicSharedMemorySize, SMEM_N128_M64);

    const int CB = 256;
    pack_qkv_w<<<(int)(((long long)NL*DM*DM3/4 + CB-1)/CB), CB>>>(Wq, Wk, Wv, hWqkv);
    pack_qkv_b<<<(NL*DM3 + CB-1)/CB, CB>>>(bq, bk, bv, bqkv);
    cvt_f2h<<<(NL*DM*DM/4 + CB-1)/CB, CB>>>(Wo, hWo, NL*DM*DM);
    cvt_f2h<<<(NL*DM*DFF/4 + CB-1)/CB, CB>>>(W1, hW1, NL*DM*DFF);
    cvt_f2h<<<(NL*DFF*DM/4 + CB-1)/CB, CB>>>(W2, hW2, NL*DFF*DM);
    cvt_f2h<<<(DM*VOCAB/4 + CB-1)/CB, CB>>>(Wfc, hWfc, DM*VOCAB);

    embed_kernel<<<(MROWS * DM + 255) / 256, 256>>>(tokens, emb, pe, x, hx);

    dim3 gQKV(MROWS / 128, DM3 / 256);  // (16, 12)
    dim3 gDD64(MROWS / 64, DM / 128);   // (32, 8) = 256 CTAs
    dim3 gDF(MROWS / 128, DFF / 256);   // (16, 16)
    dim3 gAttn(SEQ / 64, NH, BATCH);    // (8, 16, 4)

    for (int l = 0; l < NL; l++) {
        const __half* wqkv = hWqkv + (size_t)l * DM * DM3;
        const __half* wo = hWo + (size_t)l * DM * DM;
        const __half* w1 = hW1 + (size_t)l * DM * DFF;
        const __half* w2 = hW2 + (size_t)l * DFF * DM;

        hgemm<false,true,4,8><<<gQKV, 256, SMEM_N256>>>(hx, wqkv, bqkv + l * DM3, hqkv, DM3, DM);

        fattn<<<gAttn, 128>>>(hqkv, ht3);

        hgemm<false,false,2,4><<<gDD64, 256, SMEM_N128_M64>>>(ht3, wo, bo + l * DM, t0, DM, DM);
        ln_residual<<<MROWS, 256>>>(x, t0, g1 + l * DM, be1 + l * DM, hx);

        hgemm<true,true,4,8><<<gDF, 256, SMEM_N256>>>(hx, w1, b1 + l * DFF, hf1, DFF, DM);
        hgemm<false,false,2,4><<<gDD64, 256, SMEM_N128_M64>>>(hf1, w2, b2 + l * DM, t0, DM, DFF);
        ln_residual<<<MROWS, 256>>>(x, t0, g2 + l * DM, be2 + l * DM, hx);
    }

    dim3 gV(MROWS / 128, VOCAB / 256);  // (16, 125)
    hgemm<false,false,4,8><<<gV, 256, SMEM_N256>>>(hx, hWfc, bfc, out, VOCAB, DM);
}